// round 16
// baseline (speedup 1.0000x reference)
#include <cuda_runtime.h>
#include <math.h>

#define NG 1708
#define NGV 427           // NG/4 exactly
#define NH 5
#define NB 16
#define NC 34
#define NM 128            // interpolation nodes per (b,h), cubic interp
#define NSPLIT 8          // blocks per (b,h) in table stage
#define NODES_PB 16               // nodes per block
#define NSEG 64                   // segments sharing one node-group
#define SEGV 7                    // float4s per segment: 61*7 = 427 exactly
#define TPB 256

// Scratch (no allocations allowed)
__device__ float g_hbuf[2][NB * NG];    // ping-pong hidden state
__device__ float g_part[NH * NB * NG];
__device__ float g_F[NH * NB * NM];     // log2 of f(q) at nodes (shifted-k space)
__device__ float g_R[NH * NB * NM];     // r(q) = g/f at nodes
__device__ float g_prm[NH * NB * 4];    // c, q2min, dq, inv_dq

__device__ __forceinline__ float ex2(float a) {
    float r; asm("ex2.approx.f32 %0, %1;" : "=f"(r) : "f"(a)); return r;
}
__device__ __forceinline__ float lg2(float a) {
    float r; asm("lg2.approx.f32 %0, %1;" : "=f"(r) : "f"(a)); return r;
}

#define LOG2E 1.44269504088896340736f

// ---------------------------------------------------------------------------
// Table kernel. For L>0 the prologue ALSO performs the previous layer's
// LayerNorm+residual inline: head-sum a = sum_h W0p[h]*g_part[h], local
// block-reduced stats (redundant per block, deterministic, no atomics),
// hv = h_prev + ln_a*(a-mean)/(std+eps) + ln_b. Then k/v/q, midrange center
// c (exactly softmax-invariant), per-node shift s=|t|*halfr => ex2 args <= 0.
// grid (NSPLIT, NH, NB); block 256 = 4 node-groups x 64 segments, each
// thread evaluates 4 nodes over a 7-float4 segment (R14-proven body).
// Designated block (chunk==0,h==0) writes hv to the output hidden buffer.
// ---------------------------------------------------------------------------
__global__ __launch_bounds__(TPB) void table_kernel(
    int L, const float* __restrict__ x,
    const float* __restrict__ WQ, const float* __restrict__ WK,
    const float* __restrict__ WV, const float* __restrict__ W0p,
    const float* __restrict__ ln_a, const float* __restrict__ ln_b)
{
    __shared__ __align__(16) float sk[NG];
    __shared__ __align__(16) float sv[NG];
    __shared__ float sred[32];
    __shared__ float sp[4];          // (mean,inv) then (c, halfr, q2min, dq)
    __shared__ float sfg[8][8];      // per-warp partials: f[4], g[4]
    const int chunk = blockIdx.x, h = blockIdx.y, b = blockIdx.z;
    const int idx = h * NB + b;
    const int tid = threadIdx.x;
    const int hb_in  = (L == 2) ? 1 : 0;
    const int hb_out = (L == 1) ? 1 : 0;

    float4* __restrict__ sk4 = reinterpret_cast<float4*>(sk);
    float4* __restrict__ sv4 = reinterpret_cast<float4*>(sv);
    const float4* __restrict__ wq4 = reinterpret_cast<const float4*>(WQ + h * NG);
    const float4* __restrict__ wk4 = reinterpret_cast<const float4*>(WK + h * NG);
    const float4* __restrict__ wv4 = reinterpret_cast<const float4*>(WV + h * NG);
    const float4* __restrict__ hin4 = reinterpret_cast<const float4*>(
        (L == 0) ? (x + b * NG) : (&g_hbuf[hb_in][b * NG]));
    float4* __restrict__ hout4 = reinterpret_cast<float4*>(&g_hbuf[hb_out][b * NG]);

    float mean = 0.f, inv = 0.f;
    if (L > 0) {
        // Pass A: head-sum previous g_part -> a (staged in sk), local LN stats
        float w0[NH];
        #pragma unroll
        for (int hh = 0; hh < NH; hh++) w0[hh] = W0p[hh];
        float s = 0.f, ss = 0.f;
        for (int j = tid; j < NGV; j += TPB) {
            float4 a = make_float4(0.f, 0.f, 0.f, 0.f);
            #pragma unroll
            for (int hh = 0; hh < NH; hh++) {
                float4 p = reinterpret_cast<const float4*>(
                    g_part + (hh * NB + b) * NG)[j];
                a.x = fmaf(w0[hh], p.x, a.x);
                a.y = fmaf(w0[hh], p.y, a.y);
                a.z = fmaf(w0[hh], p.z, a.z);
                a.w = fmaf(w0[hh], p.w, a.w);
            }
            sk4[j] = a;
            s += (a.x + a.y) + (a.z + a.w);
            ss = fmaf(a.x, a.x, fmaf(a.y, a.y, fmaf(a.z, a.z, fmaf(a.w, a.w, ss))));
        }
        #pragma unroll
        for (int o = 16; o; o >>= 1) {
            s  += __shfl_xor_sync(0xffffffffu, s,  o);
            ss += __shfl_xor_sync(0xffffffffu, ss, o);
        }
        if ((tid & 31) == 0) { sred[tid >> 5] = s; sred[8 + (tid >> 5)] = ss; }
        __syncthreads();
        if (tid == 0) {
            float S = 0.f, SS = 0.f;
            #pragma unroll
            for (int i = 0; i < 8; i++) { S += sred[i]; SS += sred[8 + i]; }
            float m = S / (float)NG;
            float var = (SS - (float)NG * m * m) / (float)(NG - 1);
            var = fmaxf(var, 0.f);
            sp[0] = m;
            sp[1] = 1.f / (sqrtf(var) + 1e-6f);
        }
        __syncthreads();
        mean = sp[0]; inv = sp[1];
    }

    // Pass B: hv (with LN applied for L>0), k/v/q, ranges
    float kmax = -3.4e38f, kmin = 3.4e38f, qmax = -3.4e38f, qmin = 3.4e38f;
    for (int j = tid; j < NGV; j += TPB) {
        float4 hv = hin4[j];
        if (L > 0) {
            float4 a = sk4[j];
            float4 la = reinterpret_cast<const float4*>(ln_a)[j];
            float4 lb = reinterpret_cast<const float4*>(ln_b)[j];
            hv.x += fmaf(la.x * (a.x - mean), inv, lb.x);
            hv.y += fmaf(la.y * (a.y - mean), inv, lb.y);
            hv.z += fmaf(la.z * (a.z - mean), inv, lb.z);
            hv.w += fmaf(la.w * (a.w - mean), inv, lb.w);
        }
        if (chunk == 0 && h == 0) hout4[j] = hv;
        float4 wq_ = wq4[j], wk_ = wk4[j], wv_ = wv4[j];
        float4 k, v, q;
        k.x = hv.x * wk_.x; k.y = hv.y * wk_.y;
        k.z = hv.z * wk_.z; k.w = hv.w * wk_.w;
        v.x = hv.x * wv_.x; v.y = hv.y * wv_.y;
        v.z = hv.z * wv_.z; v.w = hv.w * wv_.w;
        q.x = hv.x * wq_.x * LOG2E; q.y = hv.y * wq_.y * LOG2E;
        q.z = hv.z * wq_.z * LOG2E; q.w = hv.w * wq_.w * LOG2E;
        sk4[j] = k; sv4[j] = v;
        kmax = fmaxf(kmax, fmaxf(fmaxf(k.x, k.y), fmaxf(k.z, k.w)));
        kmin = fminf(kmin, fminf(fminf(k.x, k.y), fminf(k.z, k.w)));
        qmax = fmaxf(qmax, fmaxf(fmaxf(q.x, q.y), fmaxf(q.z, q.w)));
        qmin = fminf(qmin, fminf(fminf(q.x, q.y), fminf(q.z, q.w)));
    }
    #pragma unroll
    for (int o = 16; o; o >>= 1) {
        kmax = fmaxf(kmax, __shfl_xor_sync(0xffffffffu, kmax, o));
        kmin = fminf(kmin, __shfl_xor_sync(0xffffffffu, kmin, o));
        qmax = fmaxf(qmax, __shfl_xor_sync(0xffffffffu, qmax, o));
        qmin = fminf(qmin, __shfl_xor_sync(0xffffffffu, qmin, o));
    }
    const int w = tid >> 5;
    if ((tid & 31) == 0) {
        sred[w] = kmax; sred[8 + w] = kmin;
        sred[16 + w] = qmax; sred[24 + w] = qmin;
    }
    __syncthreads();
    if (tid == 0) {
        float KM = sred[0], Km = sred[8], QM = sred[16], Qm = sred[24];
        #pragma unroll
        for (int i = 1; i < 8; i++) {
            KM = fmaxf(KM, sred[i]);      Km = fminf(Km, sred[8 + i]);
            QM = fmaxf(QM, sred[16 + i]); Qm = fminf(Qm, sred[24 + i]);
        }
        float c = 0.5f * (KM + Km);
        float halfr = 0.5f * (KM - Km);
        float dq = fmaxf((QM - Qm) / (float)(NM - 1), 1e-12f);
        sp[0] = c; sp[1] = halfr; sp[2] = Qm; sp[3] = dq;
        if (chunk == 0) {
            g_prm[idx * 4 + 0] = c;
            g_prm[idx * 4 + 1] = Qm;
            g_prm[idx * 4 + 2] = dq;
            g_prm[idx * 4 + 3] = 1.f / dq;
        }
    }
    __syncthreads();
    const float c = sp[0], halfr = sp[1], q2min = sp[2], dq = sp[3];

    // Body (identical to R14): node-group ng = tid>>6; segment = tid & 63
    const int ng = tid >> 6;
    const int seg = tid & (NSEG - 1);
    const int mbase = chunk * NODES_PB + ng * 4;
    float t[4], bias[4], f[4], g[4];
    #pragma unroll
    for (int n = 0; n < 4; n++) {
        t[n] = q2min + (float)(mbase + n) * dq;
        bias[n] = t[n] * c + fabsf(t[n]) * halfr;   // arg = t*k - bias <= 0
        f[n] = 0.f; g[n] = 0.f;
    }
    const int v0 = seg * SEGV;
    const int v1 = min(v0 + SEGV, NGV);             // segs 0..60 full, 61+ empty
    for (int jv = v0; jv < v1; jv++) {
        float4 k4 = sk4[jv];
        float4 v4 = sv4[jv];
        #pragma unroll
        for (int n = 0; n < 4; n++) {
            float e0 = ex2(fmaf(t[n], k4.x, -bias[n]));
            float e1 = ex2(fmaf(t[n], k4.y, -bias[n]));
            float e2 = ex2(fmaf(t[n], k4.z, -bias[n]));
            float e3 = ex2(fmaf(t[n], k4.w, -bias[n]));
            f[n] += (e0 + e1) + (e2 + e3);
            g[n] = fmaf(e0, v4.x, fmaf(e1, v4.y, fmaf(e2, v4.z, fmaf(e3, v4.w, g[n]))));
        }
    }
    #pragma unroll
    for (int o = 16; o; o >>= 1) {
        #pragma unroll
        for (int n = 0; n < 4; n++) {
            f[n] += __shfl_xor_sync(0xffffffffu, f[n], o);
            g[n] += __shfl_xor_sync(0xffffffffu, g[n], o);
        }
    }
    if ((tid & 31) == 0) {
        #pragma unroll
        for (int n = 0; n < 4; n++) { sfg[w][n] = f[n]; sfg[w][4 + n] = g[n]; }
    }
    __syncthreads();
    if (tid < NODES_PB) {                 // tid = ng2*4 + n
        const int ng2 = tid >> 2, n = tid & 3;
        float ff = sfg[2 * ng2][n]     + sfg[2 * ng2 + 1][n];
        float gg = sfg[2 * ng2][4 + n] + sfg[2 * ng2 + 1][4 + n];
        const int m = chunk * NODES_PB + tid;
        const float tt = q2min + (float)m * dq;
        const float ss = fabsf(tt) * halfr;
        g_F[idx * NM + m] = ss + lg2(ff);       // ff >= 1 always
        g_R[idx * NM + m] = gg / ff;
    }
}

// ---------------------------------------------------------------------------
// Interp kernel: per row i, cubic-Lagrange interpolation of F,R at q2_i;
// exact diagonal: out = r(q) - 2^(q*kt_i - F(q)) * v_i.
// grid: (7, NH, NB), block 256. Reads the hidden buffer table just wrote.
// ---------------------------------------------------------------------------
__global__ __launch_bounds__(TPB) void interp_kernel(
    int L, const float* __restrict__ WQ, const float* __restrict__ WK,
    const float* __restrict__ WV)
{
    const int h = blockIdx.y, b = blockIdx.z;
    const int idx = h * NB + b;
    const int i = blockIdx.x * TPB + threadIdx.x;
    if (i >= NG) return;
    const int hb = (L == 1) ? 1 : 0;
    const float* __restrict__ hr = &g_hbuf[hb][b * NG];

    const float c     = g_prm[idx * 4 + 0];
    const float q2min = g_prm[idx * 4 + 1];
    const float invdq = g_prm[idx * 4 + 3];

    float hv = hr[i];
    float q2 = hv * (WQ + h * NG)[i] * LOG2E;
    float kt = hv * (WK + h * NG)[i] - c;
    float v  = hv * (WV + h * NG)[i];

    float u = (q2 - q2min) * invdq;
    int j0 = (int)floorf(u);
    j0 = min(max(j0, 1), NM - 3);
    float ww = u - (float)j0;

    // Lagrange cubic weights at offset ww for nodes {-1,0,1,2}
    float a = ww + 1.f, bb = ww - 1.f, cc = ww - 2.f;
    float wm1 = -ww * bb * cc * (1.f / 6.f);
    float w0  = a * bb * cc * 0.5f;
    float w1  = -a * ww * cc * 0.5f;
    float w2  = a * ww * bb * (1.f / 6.f);

    const float* __restrict__ Fp = g_F + idx * NM + (j0 - 1);
    const float* __restrict__ Rp = g_R + idx * NM + (j0 - 1);
    float F = wm1 * Fp[0] + w0 * Fp[1] + w1 * Fp[2] + w2 * Fp[3];
    float R = wm1 * Rp[0] + w0 * Rp[1] + w1 * Rp[2] + w2 * Rp[3];

    float ed_over_f = ex2(fmaf(q2, kt, -F));   // e_i / f, <= ~1 by construction
    g_part[idx * NG + i] = R - ed_over_f * v;
}

// ---------------------------------------------------------------------------
// final: LN+residual of layer 3 (a = head-sum of last g_part), FC, log_softmax.
// grid NB, 1024 threads. Reads h2 from g_hbuf[0].
// ---------------------------------------------------------------------------
__global__ __launch_bounds__(1024) void final_kernel(
    const float* __restrict__ W0, const float* __restrict__ ln_a,
    const float* __restrict__ ln_b,
    const float* __restrict__ fc_w, const float* __restrict__ fc_b,
    float* __restrict__ out)
{
    __shared__ float4 sa4[NGV];
    __shared__ float sred[64];
    __shared__ float sb[2];
    __shared__ float slog[NC];
    __shared__ float s_ls;
    const int b = blockIdx.x, tid = threadIdx.x;
    const int w = tid >> 5, l = tid & 31;
    const float4* __restrict__ base4 =
        reinterpret_cast<const float4*>(&g_hbuf[0][b * NG]);

    float w0[NH];
    #pragma unroll
    for (int h = 0; h < NH; h++) w0[h] = W0[h];

    float s = 0.f, ss = 0.f;
    if (tid < NGV) {
        float4 a = make_float4(0.f, 0.f, 0.f, 0.f);
        #pragma unroll
        for (int h = 0; h < NH; h++) {
            float4 p = reinterpret_cast<const float4*>(
                g_part + (h * NB + b) * NG)[tid];
            a.x = fmaf(w0[h], p.x, a.x);
            a.y = fmaf(w0[h], p.y, a.y);
            a.z = fmaf(w0[h], p.z, a.z);
            a.w = fmaf(w0[h], p.w, a.w);
        }
        sa4[tid] = a;
        s = (a.x + a.y) + (a.z + a.w);
        ss = fmaf(a.x, a.x, fmaf(a.y, a.y, fmaf(a.z, a.z, a.w * a.w)));
    }
    #pragma unroll
    for (int o = 16; o; o >>= 1) {
        s  += __shfl_xor_sync(0xffffffffu, s,  o);
        ss += __shfl_xor_sync(0xffffffffu, ss, o);
    }
    if (l == 0) { sred[w] = s; sred[32 + w] = ss; }
    __syncthreads();
    if (tid == 0) {
        float S = 0.f, SS = 0.f;
        #pragma unroll
        for (int i = 0; i < 32; i++) { S += sred[i]; SS += sred[32 + i]; }
        float mean = S / (float)NG;
        float var = (SS - (float)NG * mean * mean) / (float)(NG - 1);
        var = fmaxf(var, 0.f);
        sb[0] = mean;
        sb[1] = 1.f / (sqrtf(var) + 1e-6f);
    }
    __syncthreads();
    const float mean = sb[0], inv = sb[1];

    if (tid < NGV) {
        float4 a = sa4[tid];
        float4 bs = base4[tid];
        float4 la = reinterpret_cast<const float4*>(ln_a)[tid];
        float4 lb = reinterpret_cast<const float4*>(ln_b)[tid];
        float4 o;
        o.x = bs.x + fmaf(la.x * (a.x - mean), inv, lb.x);
        o.y = bs.y + fmaf(la.y * (a.y - mean), inv, lb.y);
        o.z = bs.z + fmaf(la.z * (a.z - mean), inv, lb.z);
        o.w = bs.w + fmaf(la.w * (a.w - mean), inv, lb.w);
        sa4[tid] = o;                       // h3 row for FC
    }
    __syncthreads();

    for (int c = w; c < NC; c += 32) {
        const float4* __restrict__ wr =
            reinterpret_cast<const float4*>(fc_w + c * NG);
        float d = 0.f;
        for (int j = l; j < NGV; j += 32) {
            float4 a = sa4[j], q = wr[j];
            d = fmaf(a.x, q.x, d); d = fmaf(a.y, q.y, d);
            d = fmaf(a.z, q.z, d); d = fmaf(a.w, q.w, d);
        }
        #pragma unroll
        for (int o = 16; o; o >>= 1) d += __shfl_xor_sync(0xffffffffu, d, o);
        if (l == 0) slog[c] = d + fc_b[c];
    }
    __syncthreads();
    if (tid == 0) {
        float M = slog[0];
        #pragma unroll
        for (int c = 1; c < NC; c++) M = fmaxf(M, slog[c]);
        float sum = 0.f;
        for (int c = 0; c < NC; c++) sum += expf(slog[c] - M);
        s_ls = M + logf(sum);
    }
    __syncthreads();
    if (tid < NC) out[b * NC + tid] = slog[tid] - s_ls;
}

extern "C" void kernel_launch(void* const* d_in, const int* in_sizes, int n_in,
                              void* d_out, int out_size) {
    const float* x    = (const float*)d_in[0];
    const float* WQ[3] = {(const float*)d_in[1], (const float*)d_in[5], (const float*)d_in[9]};
    const float* WK[3] = {(const float*)d_in[2], (const float*)d_in[6], (const float*)d_in[10]};
    const float* WV[3] = {(const float*)d_in[3], (const float*)d_in[7], (const float*)d_in[11]};
    const float* W0[3] = {(const float*)d_in[4], (const float*)d_in[8], (const float*)d_in[12]};
    const float* ln_a = (const float*)d_in[13];
    const float* ln_b = (const float*)d_in[14];
    const float* fc_w = (const float*)d_in[15];
    const float* fc_b = (const float*)d_in[16];

    for (int L = 0; L < 3; L++) {
        const float* W0prev = (L == 0) ? x : W0[L - 1];   // unused when L==0
        table_kernel<<<dim3(NSPLIT, NH, NB), TPB>>>(
            L, x, WQ[L], WK[L], WV[L], W0prev, ln_a, ln_b);
        interp_kernel<<<dim3(7, NH, NB), TPB>>>(L, WQ[L], WK[L], WV[L]);
    }
    final_kernel<<<NB, 1024>>>(W0[2], ln_a, ln_b, fc_w, fc_b, (float*)d_out);
}

// round 17
// speedup vs baseline: 1.5144x; 1.5144x over previous
#include <cuda_runtime.h>
#include <math.h>

#define NG 1708
#define NGV 427           // NG/4 exactly
#define NH 5
#define NB 16
#define NC 34
#define NM 128            // interpolation nodes per (b,h), cubic interp
#define NSPLIT 8          // blocks per (b,h) in table stage
#define NODES_PB 16               // nodes per block = 2 groups x 8 nodes
#define TPB 256

// Scratch (no allocations allowed)
__device__ float g_h[NB * NG];
__device__ float g_part[NH * NB * NG];
__device__ float g_F[NH * NB * NM];     // log2 of f(q) at nodes (shifted-k space)
__device__ float g_R[NH * NB * NM];     // r(q) = g/f at nodes
__device__ float g_prm[NH * NB * 4];    // c, q2min, dq, inv_dq

__device__ __forceinline__ float ex2(float a) {
    float r; asm("ex2.approx.f32 %0, %1;" : "=f"(r) : "f"(a)); return r;
}
__device__ __forceinline__ float lg2(float a) {
    float r; asm("lg2.approx.f32 %0, %1;" : "=f"(r) : "f"(a)); return r;
}

#define LOG2E 1.44269504088896340736f

// ---------------------------------------------------------------------------
// Table kernel: per (b,h), sample F(q)=log2 sum_j 2^{q*kt_j} and
// r(q)=sum e*v/f at NM nodes over the actual q2 range. kt = k - c (midrange,
// exactly softmax-invariant). Group shift s_g = max(|t0|,|t7|)*halfr makes
// every exponent arg <= 0 within an 8-node group (no overflow), and
// f_n >= 2^(-7*dq*halfr) keeps lg2 well-conditioned.
// Exp-recurrence: e_n = e_0 * d^n with d = 2^(dq*(k-c)) -> 0.25 MUFU/eval.
// grid (NSPLIT, NH, NB); block 256 = 2 node-groups x 128 segments.
// ---------------------------------------------------------------------------
__global__ __launch_bounds__(TPB) void table_kernel(
    const float* __restrict__ x, int use_x,
    const float* __restrict__ WQ, const float* __restrict__ WK,
    const float* __restrict__ WV)
{
    __shared__ __align__(16) float sk[NG];
    __shared__ __align__(16) float sv[NG];
    __shared__ float sred[32];
    __shared__ float sp[4];          // c, halfr, q2min, dq
    __shared__ float sfg[8][16];     // per-warp partials: f[8], g[8]
    const int chunk = blockIdx.x, h = blockIdx.y, b = blockIdx.z;
    const int idx = h * NB + b;
    const int tid = threadIdx.x;
    const float4* __restrict__ hr4 =
        reinterpret_cast<const float4*>((use_x ? x : g_h) + b * NG);
    const float4* __restrict__ wq4 = reinterpret_cast<const float4*>(WQ + h * NG);
    const float4* __restrict__ wk4 = reinterpret_cast<const float4*>(WK + h * NG);
    const float4* __restrict__ wv4 = reinterpret_cast<const float4*>(WV + h * NG);
    float4* __restrict__ sk4 = reinterpret_cast<float4*>(sk);
    float4* __restrict__ sv4 = reinterpret_cast<float4*>(sv);

    float kmax = -3.4e38f, kmin = 3.4e38f, qmax = -3.4e38f, qmin = 3.4e38f;
    for (int j = tid; j < NGV; j += TPB) {      // 2 vector iterations
        float4 hv = hr4[j], wq_ = wq4[j], wk_ = wk4[j], wv_ = wv4[j];
        float4 k, v, q;
        k.x = hv.x * wk_.x; k.y = hv.y * wk_.y;
        k.z = hv.z * wk_.z; k.w = hv.w * wk_.w;
        v.x = hv.x * wv_.x; v.y = hv.y * wv_.y;
        v.z = hv.z * wv_.z; v.w = hv.w * wv_.w;
        q.x = hv.x * wq_.x * LOG2E; q.y = hv.y * wq_.y * LOG2E;
        q.z = hv.z * wq_.z * LOG2E; q.w = hv.w * wq_.w * LOG2E;
        sk4[j] = k; sv4[j] = v;
        kmax = fmaxf(kmax, fmaxf(fmaxf(k.x, k.y), fmaxf(k.z, k.w)));
        kmin = fminf(kmin, fminf(fminf(k.x, k.y), fminf(k.z, k.w)));
        qmax = fmaxf(qmax, fmaxf(fmaxf(q.x, q.y), fmaxf(q.z, q.w)));
        qmin = fminf(qmin, fminf(fminf(q.x, q.y), fminf(q.z, q.w)));
    }
    #pragma unroll
    for (int o = 16; o; o >>= 1) {
        kmax = fmaxf(kmax, __shfl_xor_sync(0xffffffffu, kmax, o));
        kmin = fminf(kmin, __shfl_xor_sync(0xffffffffu, kmin, o));
        qmax = fmaxf(qmax, __shfl_xor_sync(0xffffffffu, qmax, o));
        qmin = fminf(qmin, __shfl_xor_sync(0xffffffffu, qmin, o));
    }
    const int w = tid >> 5;
    if ((tid & 31) == 0) {
        sred[w] = kmax; sred[8 + w] = kmin;
        sred[16 + w] = qmax; sred[24 + w] = qmin;
    }
    __syncthreads();
    if (tid == 0) {
        float KM = sred[0], Km = sred[8], QM = sred[16], Qm = sred[24];
        #pragma unroll
        for (int i = 1; i < 8; i++) {
            KM = fmaxf(KM, sred[i]);      Km = fminf(Km, sred[8 + i]);
            QM = fmaxf(QM, sred[16 + i]); Qm = fminf(Qm, sred[24 + i]);
        }
        float c = 0.5f * (KM + Km);
        float halfr = 0.5f * (KM - Km);
        float dq = fmaxf((QM - Qm) / (float)(NM - 1), 1e-12f);
        sp[0] = c; sp[1] = halfr; sp[2] = Qm; sp[3] = dq;
        if (chunk == 0) {
            g_prm[idx * 4 + 0] = c;
            g_prm[idx * 4 + 1] = Qm;
            g_prm[idx * 4 + 2] = dq;
            g_prm[idx * 4 + 3] = 1.f / dq;
        }
    }
    __syncthreads();
    const float c = sp[0], halfr = sp[1], q2min = sp[2], dq = sp[3];

    // node-group ng = tid>>7 (warp-uniform); segment = tid & 127
    const int ngp = tid >> 7;
    const int seg = tid & 127;
    const int mbase = chunk * NODES_PB + ngp * 8;
    const float t0 = q2min + (float)mbase * dq;
    const float t7 = q2min + (float)(mbase + 7) * dq;
    const float sg = fmaxf(fabsf(t0), fabsf(t7)) * halfr;   // group shift
    const float c0 = -t0 * c - sg;     // arg0 = t0*k + c0 = t0*(k-c) - sg <= 0
    const float cd = -dq * c;          // darg = dq*k + cd = dq*(k-c)

    float f[8], g[8];
    #pragma unroll
    for (int n = 0; n < 8; n++) { f[n] = 0.f; g[n] = 0.f; }

    const int v0 = (seg * NGV) >> 7;                // balanced 3-4 float4s each
    const int v1 = ((seg + 1) * NGV) >> 7;
    for (int jv = v0; jv < v1; jv++) {
        float4 k4 = sk4[jv];
        float4 v4 = sv4[jv];
        #define DO_ELEM(KK, VV)                                         \
        {                                                               \
            float e  = ex2(fmaf(t0, KK, c0));                           \
            float dd = ex2(fmaf(dq, KK, cd));                           \
            f[0] += e; g[0] = fmaf(e, VV, g[0]);                        \
            _Pragma("unroll")                                           \
            for (int n = 1; n < 8; n++) {                               \
                e *= dd;                                                \
                f[n] += e; g[n] = fmaf(e, VV, g[n]);                    \
            }                                                           \
        }
        DO_ELEM(k4.x, v4.x)
        DO_ELEM(k4.y, v4.y)
        DO_ELEM(k4.z, v4.z)
        DO_ELEM(k4.w, v4.w)
        #undef DO_ELEM
    }
    #pragma unroll
    for (int o = 16; o; o >>= 1) {
        #pragma unroll
        for (int n = 0; n < 8; n++) {
            f[n] += __shfl_xor_sync(0xffffffffu, f[n], o);
            g[n] += __shfl_xor_sync(0xffffffffu, g[n], o);
        }
    }
    if ((tid & 31) == 0) {
        #pragma unroll
        for (int n = 0; n < 8; n++) { sfg[w][n] = f[n]; sfg[w][8 + n] = g[n]; }
    }
    __syncthreads();
    if (tid < NODES_PB) {                 // tid = grp*8 + n
        const int grp = tid >> 3, n = tid & 7;
        const int wb = grp * 4;           // 4 warps per node-group
        float ff = sfg[wb][n]     + sfg[wb + 1][n]
                 + sfg[wb + 2][n] + sfg[wb + 3][n];
        float gg = sfg[wb][8 + n]     + sfg[wb + 1][8 + n]
                 + sfg[wb + 2][8 + n] + sfg[wb + 3][8 + n];
        const int m = chunk * NODES_PB + tid;
        // recompute group shift with IDENTICAL fp ops as body
        const int mb2 = chunk * NODES_PB + grp * 8;
        const float u0 = q2min + (float)mb2 * dq;
        const float u7 = q2min + (float)(mb2 + 7) * dq;
        const float sg2 = fmaxf(fabsf(u0), fabsf(u7)) * halfr;
        g_F[idx * NM + m] = sg2 + lg2(ff);
        g_R[idx * NM + m] = gg / ff;
    }
}

// ---------------------------------------------------------------------------
// Interp kernel: per row i, cubic-Lagrange interpolate F and r at q2_i,
// subtract exact diagonal: out = r(q) - 2^(q*kt_i - F(q)) * v_i.
// grid: (7, NH, NB), block 256.  (verbatim R14)
// ---------------------------------------------------------------------------
__global__ __launch_bounds__(TPB) void interp_kernel(
    const float* __restrict__ x, int use_x,
    const float* __restrict__ WQ, const float* __restrict__ WK,
    const float* __restrict__ WV)
{
    const int h = blockIdx.y, b = blockIdx.z;
    const int idx = h * NB + b;
    const int i = blockIdx.x * TPB + threadIdx.x;
    if (i >= NG) return;
    const float* __restrict__ hr = (use_x ? x : g_h) + b * NG;

    const float c     = g_prm[idx * 4 + 0];
    const float q2min = g_prm[idx * 4 + 1];
    const float invdq = g_prm[idx * 4 + 3];

    float hv = hr[i];
    float q2 = hv * (WQ + h * NG)[i] * LOG2E;
    float kt = hv * (WK + h * NG)[i] - c;
    float v  = hv * (WV + h * NG)[i];

    float u = (q2 - q2min) * invdq;
    int j0 = (int)floorf(u);
    j0 = min(max(j0, 1), NM - 3);
    float ww = u - (float)j0;

    // Lagrange cubic weights at offset ww for nodes {-1,0,1,2}
    float a = ww + 1.f, bb = ww - 1.f, cc = ww - 2.f;
    float wm1 = -ww * bb * cc * (1.f / 6.f);
    float w0  = a * bb * cc * 0.5f;
    float w1  = -a * ww * cc * 0.5f;
    float w2  = a * ww * bb * (1.f / 6.f);

    const float* __restrict__ Fp = g_F + idx * NM + (j0 - 1);
    const float* __restrict__ Rp = g_R + idx * NM + (j0 - 1);
    float F = wm1 * Fp[0] + w0 * Fp[1] + w1 * Fp[2] + w2 * Fp[3];
    float R = wm1 * Rp[0] + w0 * Rp[1] + w1 * Rp[2] + w2 * Rp[3];

    float ed_over_f = ex2(fmaf(q2, kt, -F));   // e_i / f, <= ~1 by construction
    g_part[idx * NG + i] = R - ed_over_f * v;
}

// ---------------------------------------------------------------------------
// ln_fc: verbatim from the passing R4/R10/R14 kernel.
// ---------------------------------------------------------------------------
__global__ __launch_bounds__(1024) void ln_fc_kernel(
    const float* __restrict__ x, int use_x,
    const float* __restrict__ W0, const float* __restrict__ ln_a,
    const float* __restrict__ ln_b, int do_fc,
    const float* __restrict__ fc_w, const float* __restrict__ fc_b,
    float* __restrict__ out)
{
    __shared__ float4 sa4[NGV];
    __shared__ float sred[64];
    __shared__ float sb[2];
    __shared__ float slog[NC];
    __shared__ float s_ls;
    const int b = blockIdx.x, tid = threadIdx.x;
    const int w = tid >> 5, l = tid & 31;
    const float4* __restrict__ base4 =
        reinterpret_cast<const float4*>((use_x ? x : g_h) + b * NG);

    float w0[NH];
    #pragma unroll
    for (int h = 0; h < NH; h++) w0[h] = W0[h];

    float s = 0.f, ss = 0.f;
    if (tid < NGV) {
        float4 a = make_float4(0.f, 0.f, 0.f, 0.f);
        #pragma unroll
        for (int h = 0; h < NH; h++) {
            float4 p = reinterpret_cast<const float4*>(
                g_part + (h * NB + b) * NG)[tid];
            a.x = fmaf(w0[h], p.x, a.x);
            a.y = fmaf(w0[h], p.y, a.y);
            a.z = fmaf(w0[h], p.z, a.z);
            a.w = fmaf(w0[h], p.w, a.w);
        }
        sa4[tid] = a;
        s = (a.x + a.y) + (a.z + a.w);
        ss = fmaf(a.x, a.x, fmaf(a.y, a.y, fmaf(a.z, a.z, a.w * a.w)));
    }
    #pragma unroll
    for (int o = 16; o; o >>= 1) {
        s  += __shfl_xor_sync(0xffffffffu, s,  o);
        ss += __shfl_xor_sync(0xffffffffu, ss, o);
    }
    if (l == 0) { sred[w] = s; sred[32 + w] = ss; }
    __syncthreads();
    if (tid == 0) {
        float S = 0.f, SS = 0.f;
        #pragma unroll
        for (int i = 0; i < 32; i++) { S += sred[i]; SS += sred[32 + i]; }
        float mean = S / (float)NG;
        float var = (SS - (float)NG * mean * mean) / (float)(NG - 1);
        var = fmaxf(var, 0.f);
        sb[0] = mean;
        sb[1] = 1.f / (sqrtf(var) + 1e-6f);
    }
    __syncthreads();
    const float mean = sb[0], inv = sb[1];

    if (tid < NGV) {
        float4 a = sa4[tid];
        float4 bs = base4[tid];
        float4 la = reinterpret_cast<const float4*>(ln_a)[tid];
        float4 lb = reinterpret_cast<const float4*>(ln_b)[tid];
        float4 o;
        o.x = bs.x + fmaf(la.x * (a.x - mean), inv, lb.x);
        o.y = bs.y + fmaf(la.y * (a.y - mean), inv, lb.y);
        o.z = bs.z + fmaf(la.z * (a.z - mean), inv, lb.z);
        o.w = bs.w + fmaf(la.w * (a.w - mean), inv, lb.w);
        reinterpret_cast<float4*>(g_h + b * NG)[tid] = o;
        sa4[tid] = o;                       // keep h3 row for fused FC
    }

    if (!do_fc) return;
    __syncthreads();

    for (int c = w; c < NC; c += 32) {
        const float4* __restrict__ wr =
            reinterpret_cast<const float4*>(fc_w + c * NG);
        float d = 0.f;
        for (int j = l; j < NGV; j += 32) {
            float4 a = sa4[j], q = wr[j];
            d = fmaf(a.x, q.x, d); d = fmaf(a.y, q.y, d);
            d = fmaf(a.z, q.z, d); d = fmaf(a.w, q.w, d);
        }
        #pragma unroll
        for (int o = 16; o; o >>= 1) d += __shfl_xor_sync(0xffffffffu, d, o);
        if (l == 0) slog[c] = d + fc_b[c];
    }
    __syncthreads();
    if (tid == 0) {
        float M = slog[0];
        #pragma unroll
        for (int c = 1; c < NC; c++) M = fmaxf(M, slog[c]);
        float sum = 0.f;
        for (int c = 0; c < NC; c++) sum += expf(slog[c] - M);
        s_ls = M + logf(sum);
    }
    __syncthreads();
    if (tid < NC) out[b * NC + tid] = slog[tid] - s_ls;
}

extern "C" void kernel_launch(void* const* d_in, const int* in_sizes, int n_in,
                              void* d_out, int out_size) {
    const float* x    = (const float*)d_in[0];
    const float* WQ[3] = {(const float*)d_in[1], (const float*)d_in[5], (const float*)d_in[9]};
    const float* WK[3] = {(const float*)d_in[2], (const float*)d_in[6], (const float*)d_in[10]};
    const float* WV[3] = {(const float*)d_in[3], (const float*)d_in[7], (const float*)d_in[11]};
    const float* W0[3] = {(const float*)d_in[4], (const float*)d_in[8], (const float*)d_in[12]};
    const float* ln_a = (const float*)d_in[13];
    const float* ln_b = (const float*)d_in[14];
    const float* fc_w = (const float*)d_in[15];
    const float* fc_b = (const float*)d_in[16];

    for (int L = 0; L < 3; L++) {
        int ux = (L == 0) ? 1 : 0;
        table_kernel<<<dim3(NSPLIT, NH, NB), TPB>>>(x, ux, WQ[L], WK[L], WV[L]);
        interp_kernel<<<dim3(7, NH, NB), TPB>>>(x, ux, WQ[L], WK[L], WV[L]);
        ln_fc_kernel<<<NB, 1024>>>(x, ux, W0[L], ln_a, ln_b,
                                   L == 2 ? 1 : 0, fc_w, fc_b, (float*)d_out);
    }
}